// round 7
// baseline (speedup 1.0000x reference)
#include <cuda_runtime.h>
#include <cstdint>

#define M_DIM 8192
#define N_DIM 8192
#define C_DIM 80
#define CAP   1024      // per-class list capacity (mean count 102)

// R[c][n] = base[n] - pre_cls[n][c]  (2.6 MB, L2-resident)
__device__ float g_R[C_DIM * N_DIM];
__device__ int   g_list[C_DIM * CAP];
__device__ int   g_cnt[C_DIM];

// ---------------------------------------------------------------------------
// Kernel 1: build R (coalesced loads, shared transpose, folded subtraction).
// Block 0 also zeroes g_cnt for the bucketizer (stream-serialized after us).
// ---------------------------------------------------------------------------
#define TN   64
#define SPAD 84

__global__ __launch_bounds__(256)
void build_R_kernel(const float* __restrict__ pre)
{
    __shared__ float S[TN * SPAD];
    __shared__ float psum[TN * 4];
    __shared__ float base_sm[TN];

    const int tid = threadIdx.x;
    const int n0  = blockIdx.x * TN;

    if (blockIdx.x == 0 && tid < C_DIM) g_cnt[tid] = 0;

    // Coalesced load of 64 rows x 80 floats (contiguous 20 KB region).
    const float4* src = (const float4*)(pre + (size_t)n0 * C_DIM);
    for (int i = tid; i < TN * C_DIM / 4; i += 256) {
        float4 v = src[i];
        int l = 4 * i;
        *(float4*)&S[(l / C_DIM) * SPAD + (l % C_DIM)] = v;
    }
    __syncthreads();

    // Softplus partial sums: 4 threads per row, 20 c's each.
    {
        int r = tid & 63;
        int q = tid >> 6;
        float s = 0.0f;
#pragma unroll
        for (int c = q * 20; c < q * 20 + 20; ++c) {
            float x = S[r * SPAD + c];
            s += fmaxf(x, 0.0f) + log1pf(__expf(-fabsf(x)));
        }
        psum[q * TN + r] = s;
    }
    __syncthreads();
    if (tid < TN)
        base_sm[tid] = psum[tid] + psum[TN + tid] + psum[2 * TN + tid] + psum[3 * TN + tid];
    __syncthreads();

    for (int j = tid; j < C_DIM * TN; j += 256) {
        int c = j >> 6;
        int k = j & 63;
        g_R[(size_t)c * N_DIM + n0 + k] = base_sm[k] - S[k * SPAD + c];
    }
}

// ---------------------------------------------------------------------------
// Kernel 2: bucket m-indices by class. 8192 threads, one global atomic each
// over 80 addresses (spread contention, L2 atomic unit). ~1.5 us.
// Order within a bucket is arbitrary; output is order-independent.
// ---------------------------------------------------------------------------
__global__ __launch_bounds__(256)
void bucketize_kernel(const int* __restrict__ gt)
{
    const int m = blockIdx.x * 256 + threadIdx.x;
    const int g = __ldg(&gt[m]);
    int p = atomicAdd(&g_cnt[g], 1);
    if (p < CAP) g_list[g * CAP + p] = m;
}

// ---------------------------------------------------------------------------
// Kernel 3: out[m][:] = R[g][:] for every m in class g's bucket.
// Each block holds the FULL 8192-float row R[g] in registers (8 float4 per
// thread) and replays it: 8 independent STG.128 per m-row, 32 KB contiguous
// per row. ZERO reads in the 256 MB store stream -> LTS sees writes only.
// grid = (SPLIT, C_DIM)
// ---------------------------------------------------------------------------
#define SPLIT 5
#define SMAX  ((CAP + SPLIT - 1) / SPLIT + 4)

__global__ __launch_bounds__(256)
void gather_store_kernel(float* __restrict__ out)
{
    __shared__ int sm[SMAX];

    const int tid = threadIdx.x;
    const int g   = blockIdx.y;
    const int s   = blockIdx.x;

    const int cnt = min(g_cnt[g], CAP);
    const int mb  = cnt * s / SPLIT;
    const int me  = cnt * (s + 1) / SPLIT;
    const int len = me - mb;

    // Full row R[g] into registers: 8 float4 per thread (32 regs).
    float4 v[8];
    const float4* Rrow = (const float4*)(g_R + (size_t)g * N_DIM);
#pragma unroll
    for (int k = 0; k < 8; ++k)
        v[k] = __ldcg(Rrow + k * 256 + tid);

    for (int i = tid; i < len; i += 256)
        sm[i] = g_list[g * CAP + mb + i];
    __syncthreads();

    for (int j = 0; j < len; ++j) {
        float4* dst = (float4*)(out + (size_t)sm[j] * N_DIM) + tid;
#pragma unroll
        for (int k = 0; k < 8; ++k)
            __stcs(dst + k * 256, v[k]);
    }
}

// ---------------------------------------------------------------------------
extern "C" void kernel_launch(void* const* d_in, const int* in_sizes, int n_in,
                              void* d_out, int out_size)
{
    const int*   gt  = (const int*)d_in[0];      // gt_kind_ind [M]
    const float* pre = (const float*)d_in[1];    // pre_cls [N, C]
    float*       out = (float*)d_out;            // [M, N] f32

    build_R_kernel<<<N_DIM / TN, 256>>>(pre);    // also zeroes g_cnt
    bucketize_kernel<<<M_DIM / 256, 256>>>(gt);

    dim3 grid(SPLIT, C_DIM);
    gather_store_kernel<<<grid, 256>>>(out);
}

// round 8
// speedup vs baseline: 1.2325x; 1.2325x over previous
#include <cuda_runtime.h>
#include <cstdint>

#define M_DIM 8192
#define N_DIM 8192
#define C_DIM 80

// R[c][n] = base[n] - pre_cls[n][c]   (2.6 MB, L2-resident)
// out[m][:] = R[gt[m]][:]  (gather-broadcast copy).
__device__ float g_R[C_DIM * N_DIM];

// ---------------------------------------------------------------------------
// Kernel A: build R. 256 blocks x 32 n-rows. Coalesced float4 loads into a
// shared tile, softplus with 8 threads/row (10 c's each) + shfl reduce,
// fast-math softplus (budget: rel tol 1e-3, we sit at ~1e-7).
// ---------------------------------------------------------------------------
#define TN   32
#define SPAD 88

__global__ __launch_bounds__(256)
void build_R_kernel(const float* __restrict__ pre)
{
    __shared__ float S[TN * SPAD];
    __shared__ float base_sm[TN];

    const int tid = threadIdx.x;
    const int n0  = blockIdx.x * TN;

    // Coalesced load: 32 rows x 80 floats = 640 float4 (contiguous 10 KB).
    const float4* src = (const float4*)(pre + (size_t)n0 * C_DIM);
#pragma unroll
    for (int i = tid; i < TN * C_DIM / 4; i += 256) {
        float4 v = src[i];
        int l = 4 * i;
        *(float4*)&S[(l / C_DIM) * SPAD + (l % C_DIM)] = v;
    }
    __syncthreads();

    // Softplus: 8 threads per row, 10 c's each, subwarp shfl reduce.
    {
        const int r = tid >> 3;        // row 0..31
        const int q = tid & 7;         // subthread 0..7
        float s = 0.0f;
#pragma unroll
        for (int i = 0; i < 10; ++i) {
            float x = S[r * SPAD + q * 10 + i];
            // softplus = max(x,0) + log(1 + exp(-|x|))  (fast-math)
            s += fmaxf(x, 0.0f) + __logf(1.0f + __expf(-fabsf(x)));
        }
        s += __shfl_xor_sync(0xffffffffu, s, 4);
        s += __shfl_xor_sync(0xffffffffu, s, 2);
        s += __shfl_xor_sync(0xffffffffu, s, 1);
        if (q == 0) base_sm[r] = s;
    }
    __syncthreads();

    // R[c][n0+k] = base[k] - S[k][c]; 32-float coalesced runs per c.
#pragma unroll
    for (int j = tid; j < C_DIM * TN; j += 256) {
        int c = j >> 5;
        int k = j & 31;
        g_R[(size_t)c * N_DIM + n0 + k] = base_sm[k] - S[k * SPAD + c];
    }
}

// ---------------------------------------------------------------------------
// Kernel B: out[m][n] = R[gt[m]][n].
// Best-measured writer config (R1 structure): 256 threads x float4 along n,
// 8 m-rows per block. Reads hit L2 (__ldcg), streaming stores (__stcs).
// DRAM write path (~6.4 TB/s effective) is the ceiling; reads ride free.
// ---------------------------------------------------------------------------
#define BTHREADS 256
#define MROWS    8
#define N4       (N_DIM / 4)     // 2048 float4 per row

__global__ __launch_bounds__(BTHREADS)
void out_kernel(const int* __restrict__ gt, float4* __restrict__ out)
{
    const int n4 = blockIdx.x * BTHREADS + threadIdx.x;
    const int m0 = blockIdx.y * MROWS;

    __shared__ int sg[MROWS];
    if (threadIdx.x < MROWS) sg[threadIdx.x] = __ldg(&gt[m0 + threadIdx.x]);
    __syncthreads();

#pragma unroll
    for (int r = 0; r < MROWS; ++r) {
        const float4 v = __ldcg((const float4*)(g_R + (size_t)sg[r] * N_DIM) + n4);
        __stcs(&out[(size_t)(m0 + r) * N4 + n4], v);
    }
}

// ---------------------------------------------------------------------------
extern "C" void kernel_launch(void* const* d_in, const int* in_sizes, int n_in,
                              void* d_out, int out_size)
{
    const int*   gt  = (const int*)d_in[0];      // gt_kind_ind [M]
    const float* pre = (const float*)d_in[1];    // pre_cls [N, C]
    float4*      out = (float4*)d_out;           // [M, N] f32

    build_R_kernel<<<N_DIM / TN, 256>>>(pre);    // 256 blocks

    dim3 grid(N4 / BTHREADS, M_DIM / MROWS);     // (8, 1024)
    out_kernel<<<grid, BTHREADS>>>(gt, out);
}

// round 10
// speedup vs baseline: 1.2987x; 1.0537x over previous
#include <cuda_runtime.h>
#include <cstdint>

#define M_DIM 8192
#define N_DIM 8192
#define C_DIM 80

// R[c][n] = base[n] - pre_cls[n][c]   (2.6 MB; rows L1/L2-resident)
// out[m][:] = R[gt[m]][:]  (gather-broadcast copy).
__device__ float g_R[C_DIM * N_DIM];

// ---------------------------------------------------------------------------
// Kernel A: build R. 256 blocks x 32 n-rows. Coalesced float4 loads into a
// shared tile, softplus with 8 threads/row (10 c's each) + shfl reduce,
// fast-math softplus (tol budget 1e-3, we sit at ~6e-8). ~3 us measured.
// ---------------------------------------------------------------------------
#define TN   32
#define SPAD 88

__global__ __launch_bounds__(256)
void build_R_kernel(const float* __restrict__ pre)
{
    __shared__ float S[TN * SPAD];
    __shared__ float base_sm[TN];

    const int tid = threadIdx.x;
    const int n0  = blockIdx.x * TN;

    // Coalesced load: 32 rows x 80 floats = 640 float4 (contiguous 10 KB).
    const float4* src = (const float4*)(pre + (size_t)n0 * C_DIM);
#pragma unroll
    for (int i = tid; i < TN * C_DIM / 4; i += 256) {
        float4 v = src[i];
        int l = 4 * i;
        *(float4*)&S[(l / C_DIM) * SPAD + (l % C_DIM)] = v;
    }
    __syncthreads();

    // Softplus: 8 threads per row, 10 c's each, subwarp shfl reduce.
    {
        const int r = tid >> 3;        // row 0..31
        const int q = tid & 7;         // subthread 0..7
        float s = 0.0f;
#pragma unroll
        for (int i = 0; i < 10; ++i) {
            float x = S[r * SPAD + q * 10 + i];
            s += fmaxf(x, 0.0f) + __logf(1.0f + __expf(-fabsf(x)));
        }
        s += __shfl_xor_sync(0xffffffffu, s, 4);
        s += __shfl_xor_sync(0xffffffffu, s, 2);
        s += __shfl_xor_sync(0xffffffffu, s, 1);
        if (q == 0) base_sm[r] = s;
    }
    __syncthreads();

    // R[c][n0+k] = base[k] - S[k][c]; 32-float coalesced runs per c.
#pragma unroll
    for (int j = tid; j < C_DIM * TN; j += 256) {
        int c = j >> 5;
        int k = j & 31;
        g_R[(size_t)c * N_DIM + n0 + k] = base_sm[k] - S[k * SPAD + c];
    }
}

// ---------------------------------------------------------------------------
// Kernel B: out[m][n] = R[gt[m]][n].
// Best-measured writer (R1 config): 256 threads x float4 along n, 8 m-rows
// per block, __ldg reads (L1-allocating: only 80 distinct 32KB rows -> high
// L1 hit rate, short load latency), __stcs streaming stores (protect L2 from
// the 256 MB output stream). All 8 loads issued before the store burst.
// ---------------------------------------------------------------------------
#define BTHREADS 256
#define MROWS    8
#define N4       (N_DIM / 4)     // 2048 float4 per row

__global__ __launch_bounds__(BTHREADS)
void out_kernel(const int* __restrict__ gt, float4* __restrict__ out)
{
    const int n4 = blockIdx.x * BTHREADS + threadIdx.x;
    const int m0 = blockIdx.y * MROWS;

    __shared__ int sg[MROWS];
    if (threadIdx.x < MROWS) sg[threadIdx.x] = __ldg(&gt[m0 + threadIdx.x]);
    __syncthreads();

    // Issue all 8 independent loads first (deep MLP), then the store burst.
    float4 v[MROWS];
#pragma unroll
    for (int r = 0; r < MROWS; ++r)
        v[r] = __ldg((const float4*)(g_R + (size_t)sg[r] * N_DIM) + n4);

#pragma unroll
    for (int r = 0; r < MROWS; ++r)
        __stcs(&out[(size_t)(m0 + r) * N4 + n4], v[r]);
}

// ---------------------------------------------------------------------------
extern "C" void kernel_launch(void* const* d_in, const int* in_sizes, int n_in,
                              void* d_out, int out_size)
{
    const int*   gt  = (const int*)d_in[0];      // gt_kind_ind [M]
    const float* pre = (const float*)d_in[1];    // pre_cls [N, C]
    float4*      out = (float4*)d_out;           // [M, N] f32

    build_R_kernel<<<N_DIM / TN, 256>>>(pre);    // 256 blocks, ~3 us

    dim3 grid(N4 / BTHREADS, M_DIM / MROWS);     // (8, 1024)
    out_kernel<<<grid, BTHREADS>>>(gt, out);
}